// round 1
// baseline (speedup 1.0000x reference)
#include <cuda_runtime.h>
#include <math.h>

#define Nn 50000
#define Ee 800000
#define Hh 128
#define Gg 128

// ---------------- scratch (allocation-free: __device__ globals) --------------
__device__ float g_h1[Nn * Hh];
__device__ float g_h2[Nn * Hh];
__device__ float g_agg[Nn * Hh];
__device__ float g_invdeg[Nn];
__device__ float g_pool[Gg * Hh];
__device__ float g_cnt[Gg];

// ---------------- utility kernels -------------------------------------------
__global__ void zero_kernel(float* __restrict__ p, int n) {
    int i = blockIdx.x * blockDim.x + threadIdx.x;
    if (i < n) p[i] = 0.0f;
}

__global__ void deg_kernel(const int* __restrict__ el) {
    int e = blockIdx.x * blockDim.x + threadIdx.x;
    if (e < Ee) atomicAdd(&g_invdeg[el[2 * e + 1]], 1.0f);
}

__global__ void invdeg_kernel() {
    int i = blockIdx.x * blockDim.x + threadIdx.x;
    if (i < Nn) g_invdeg[i] = 1.0f / fmaxf(g_invdeg[i], 1.0f);
}

// ---------------- edge scatter: agg[dst] += h[src] ---------------------------
// One warp per edge. Lane c handles float4 chunk c of the 128-float row.
// Row read is a fully-coalesced 512B load; h fits in L2 (25.6MB << 126MB).
__global__ void scatter_kernel(const float* __restrict__ hin,
                               const int2* __restrict__ el) {
    int tid = blockIdx.x * blockDim.x + threadIdx.x;
    int e = tid >> 5;
    if (e >= Ee) return;
    int c = tid & 31;
    int2 ed = el[e];  // same-address broadcast within warp
    const float4* src = reinterpret_cast<const float4*>(hin + (size_t)ed.x * Hh);
    float4 v = src[c];
    float* dst = g_agg + (size_t)ed.y * Hh + c * 4;
    atomicAdd(dst + 0, v.x);
    atomicAdd(dst + 1, v.y);
    atomicAdd(dst + 2, v.z);
    atomicAdd(dst + 3, v.w);
}

// ---------------- fused dual GEMM + bias + relu ------------------------------
// out[n,c] = relu( (agg[n,:]*invdeg[n]) @ Wl[:,c] + h[n,:] @ Wr[:,c] + b[c] )
// Tile: 64 nodes x 128 cols, BK=16, 256 threads, 4x8 register tile per thread.
__global__ void __launch_bounds__(256)
gemm_fused(const float* __restrict__ Adata, const float* __restrict__ Hdata,
           const float* __restrict__ Wl, const float* __restrict__ Wr,
           const float* __restrict__ bias, float* __restrict__ out) {
    __shared__ float As[64][17];
    __shared__ float Hs[64][17];
    __shared__ float Wls[16][128];
    __shared__ float Wrs[16][128];

    int tid = threadIdx.x;
    int tx = tid & 15;   // col group: cols tx + 16*j
    int ty = tid >> 4;   // row group: rows ty*4 + i
    int n0 = blockIdx.x * 64;

    float acc[4][8];
#pragma unroll
    for (int i = 0; i < 4; i++)
#pragma unroll
        for (int j = 0; j < 8; j++) acc[i][j] = 0.0f;

    for (int k0 = 0; k0 < 128; k0 += 16) {
        // load A (scaled by invdeg) and H tiles
        for (int i = tid; i < 64 * 16; i += 256) {
            int r = i >> 4, k = i & 15;
            int n = n0 + r;
            float a = 0.0f, h = 0.0f;
            if (n < Nn) {
                float inv = g_invdeg[n];
                a = Adata[(size_t)n * 128 + k0 + k] * inv;
                h = Hdata[(size_t)n * 128 + k0 + k];
            }
            As[r][k] = a;
            Hs[r][k] = h;
        }
        // load weight tiles (coalesced)
        for (int i = tid; i < 16 * 128; i += 256) {
            int r = i >> 7, c = i & 127;
            Wls[r][c] = Wl[(k0 + r) * 128 + c];
            Wrs[r][c] = Wr[(k0 + r) * 128 + c];
        }
        __syncthreads();

#pragma unroll
        for (int kk = 0; kk < 16; kk++) {
            float a[4], h[4];
#pragma unroll
            for (int i = 0; i < 4; i++) {
                a[i] = As[ty * 4 + i][kk];
                h[i] = Hs[ty * 4 + i][kk];
            }
            float wl[8], wr[8];
#pragma unroll
            for (int j = 0; j < 8; j++) {
                wl[j] = Wls[kk][tx + 16 * j];
                wr[j] = Wrs[kk][tx + 16 * j];
            }
#pragma unroll
            for (int i = 0; i < 4; i++)
#pragma unroll
                for (int j = 0; j < 8; j++)
                    acc[i][j] += a[i] * wl[j] + h[i] * wr[j];
        }
        __syncthreads();
    }

#pragma unroll
    for (int i = 0; i < 4; i++) {
        int n = n0 + ty * 4 + i;
        if (n < Nn) {
#pragma unroll
            for (int j = 0; j < 8; j++) {
                int c = tx + 16 * j;
                out[(size_t)n * 128 + c] = fmaxf(acc[i][j] + bias[c], 0.0f);
            }
        }
    }
}

// ---------------- graph pooling ----------------------------------------------
__global__ void pool_kernel(const float* __restrict__ h,
                            const int* __restrict__ batch) {
    int tid = blockIdx.x * blockDim.x + threadIdx.x;
    if (tid >= Nn * Hh) return;
    int n = tid >> 7;
    int j = tid & 127;
    atomicAdd(&g_pool[batch[n] * 128 + j], h[tid]);
}

__global__ void cnt_kernel(const int* __restrict__ batch) {
    int n = blockIdx.x * blockDim.x + threadIdx.x;
    if (n < Nn) atomicAdd(&g_cnt[batch[n]], 1.0f);
}

// ---------------- final MLP head ----------------------------------------------
__global__ void mlp_kernel(const float* __restrict__ Wf1,
                           const float* __restrict__ bf1,
                           const float* __restrict__ Wf2,
                           const float* __restrict__ bf2,
                           float* __restrict__ out) {
    __shared__ float gs[128];
    __shared__ float red[128];
    int j = threadIdx.x;
    for (int gi = 0; gi < Gg; gi++) {
        float inv = 1.0f / fmaxf(g_cnt[gi], 1.0f);
        gs[j] = g_pool[gi * 128 + j] * inv;
        __syncthreads();
        float acc = bf1[j];
#pragma unroll 8
        for (int k = 0; k < 128; k++) acc += gs[k] * Wf1[k * 128 + j];
        float hid = fmaxf(acc, 0.0f);
        red[j] = hid * Wf2[j];
        __syncthreads();
        for (int s = 64; s > 0; s >>= 1) {
            if (j < s) red[j] += red[j + s];
            __syncthreads();
        }
        if (j == 0) out[gi] = 1.0f / (1.0f + expf(-(red[0] + bf2[0])));
        __syncthreads();
    }
}

// ---------------- launch -------------------------------------------------------
extern "C" void kernel_launch(void* const* d_in, const int* in_sizes, int n_in,
                              void* d_out, int out_size) {
    const float* x = (const float*)d_in[0];
    const int* el = (const int*)d_in[1];
    const int* batch = (const int*)d_in[2];
    const float *Wl[5], *Wr[5], *bb[5];
    for (int i = 0; i < 5; i++) {
        Wl[i] = (const float*)d_in[3 + 3 * i];
        Wr[i] = (const float*)d_in[4 + 3 * i];
        bb[i] = (const float*)d_in[5 + 3 * i];
    }
    const float* Wf1 = (const float*)d_in[18];
    const float* bf1 = (const float*)d_in[19];
    const float* Wf2 = (const float*)d_in[20];
    const float* bf2 = (const float*)d_in[21];
    float* out = (float*)d_out;

    float *h1, *h2, *agg, *invdeg, *pool, *cnt;
    cudaGetSymbolAddress((void**)&h1, g_h1);
    cudaGetSymbolAddress((void**)&h2, g_h2);
    cudaGetSymbolAddress((void**)&agg, g_agg);
    cudaGetSymbolAddress((void**)&invdeg, g_invdeg);
    cudaGetSymbolAddress((void**)&pool, g_pool);
    cudaGetSymbolAddress((void**)&cnt, g_cnt);

    // degree -> inverse degree
    zero_kernel<<<(Nn + 255) / 256, 256>>>(invdeg, Nn);
    deg_kernel<<<(Ee + 255) / 256, 256>>>(el);
    invdeg_kernel<<<(Nn + 255) / 256, 256>>>();

    // 5 SAGE layers
    const float* hin = x;
    for (int l = 0; l < 5; l++) {
        zero_kernel<<<(Nn * Hh + 255) / 256, 256>>>(agg, Nn * Hh);
        scatter_kernel<<<(Ee * 32) / 256, 256>>>(hin, (const int2*)el);
        float* ho = (l & 1) ? h2 : h1;
        gemm_fused<<<(Nn + 63) / 64, 256>>>(agg, hin, Wl[l], Wr[l], bb[l], ho);
        hin = ho;
    }

    // mean pool per graph
    zero_kernel<<<(Gg * Hh + 255) / 256, 256>>>(pool, Gg * Hh);
    zero_kernel<<<1, 256>>>(cnt, Gg);
    pool_kernel<<<(Nn * Hh + 255) / 256, 256>>>(hin, batch);
    cnt_kernel<<<(Nn + 255) / 256, 256>>>(batch);

    // MLP head + sigmoid
    mlp_kernel<<<1, 128>>>(Wf1, bf1, Wf2, bf2, out);
}

// round 2
// speedup vs baseline: 1.9134x; 1.9134x over previous
#include <cuda_runtime.h>
#include <math.h>

#define Nn 50000
#define Ee 800000
#define Hh 128
#define Gg 128

// ---------------- scratch (allocation-free: __device__ globals) --------------
__device__ float g_h1[Nn * Hh];
__device__ float g_h2[Nn * Hh];
__device__ float g_agg[Nn * Hh];
__device__ float g_invdeg[Nn];
__device__ float g_pool[Gg * Hh];
__device__ int   g_cntn[Nn];
__device__ int   g_rowptr[Nn + 1];
__device__ int   g_cursor[Nn];
__device__ int   g_srcidx[Ee];

// ---------------- f32x2 helpers ----------------------------------------------
__device__ __forceinline__ unsigned long long pack2(float lo, float hi) {
    unsigned long long r;
    asm("mov.b64 %0, {%1,%2};" : "=l"(r) : "f"(lo), "f"(hi));
    return r;
}
__device__ __forceinline__ unsigned long long fma2(unsigned long long a,
                                                   unsigned long long b,
                                                   unsigned long long c) {
    unsigned long long d;
    asm("fma.rn.f32x2 %0, %1, %2, %3;" : "=l"(d) : "l"(a), "l"(b), "l"(c));
    return d;
}
__device__ __forceinline__ void unpack2(unsigned long long v, float& lo, float& hi) {
    lo = __uint_as_float((unsigned)(v & 0xffffffffull));
    hi = __uint_as_float((unsigned)(v >> 32));
}

// ---------------- CSR build ----------------------------------------------------
__global__ void zero_int_kernel(int* __restrict__ p, int n) {
    int i = blockIdx.x * blockDim.x + threadIdx.x;
    if (i < n) p[i] = 0;
}

__global__ void hist_kernel(const int2* __restrict__ el) {
    int e = blockIdx.x * blockDim.x + threadIdx.x;
    if (e < Ee) atomicAdd(&g_cntn[el[e].y], 1);
}

// single-block exclusive scan over 50k degree counts; also emits invdeg
__global__ void scan_kernel() {
    __shared__ int sh[1024];
    __shared__ int carry;
    int tid = threadIdx.x;
    if (tid == 0) carry = 0;
    __syncthreads();
    for (int base = 0; base < Nn; base += 1024) {
        int i = base + tid;
        int v = (i < Nn) ? g_cntn[i] : 0;
        if (i < Nn) g_invdeg[i] = 1.0f / fmaxf((float)v, 1.0f);
        sh[tid] = v;
        __syncthreads();
        for (int off = 1; off < 1024; off <<= 1) {
            int t = (tid >= off) ? sh[tid - off] : 0;
            __syncthreads();
            sh[tid] += t;
            __syncthreads();
        }
        int excl = carry + sh[tid] - v;
        if (i < Nn) { g_rowptr[i] = excl; g_cursor[i] = excl; }
        __syncthreads();
        if (tid == 1023) carry += sh[1023];
        __syncthreads();
    }
    if (tid == 0) g_rowptr[Nn] = Ee;
}

__global__ void fill_kernel(const int2* __restrict__ el) {
    int e = blockIdx.x * blockDim.x + threadIdx.x;
    if (e < Ee) {
        int2 ed = el[e];
        int pos = atomicAdd(&g_cursor[ed.y], 1);
        g_srcidx[pos] = ed.x;
    }
}

// ---------------- neighbor gather: agg[n] = invdeg[n] * sum h[nbrs] ------------
// one warp per node; lane c handles float4 chunk c of the 128-float row.
__global__ void __launch_bounds__(256)
gather_kernel(const float* __restrict__ hin) {
    int w = (blockIdx.x * blockDim.x + threadIdx.x) >> 5;
    if (w >= Nn) return;
    int lane = threadIdx.x & 31;
    int beg = g_rowptr[w], end = g_rowptr[w + 1];
    float4 acc = {0.f, 0.f, 0.f, 0.f};
    int i = beg;
    for (; i + 1 < end; i += 2) {
        int s0 = g_srcidx[i];
        int s1 = g_srcidx[i + 1];
        float4 v0 = reinterpret_cast<const float4*>(hin + (size_t)s0 * Hh)[lane];
        float4 v1 = reinterpret_cast<const float4*>(hin + (size_t)s1 * Hh)[lane];
        acc.x += v0.x + v1.x;
        acc.y += v0.y + v1.y;
        acc.z += v0.z + v1.z;
        acc.w += v0.w + v1.w;
    }
    if (i < end) {
        int s0 = g_srcidx[i];
        float4 v0 = reinterpret_cast<const float4*>(hin + (size_t)s0 * Hh)[lane];
        acc.x += v0.x; acc.y += v0.y; acc.z += v0.z; acc.w += v0.w;
    }
    float inv = g_invdeg[w];
    acc.x *= inv; acc.y *= inv; acc.z *= inv; acc.w *= inv;
    reinterpret_cast<float4*>(g_agg + (size_t)w * Hh)[lane] = acc;
}

// ---------------- fused dual GEMM + bias + relu (f32x2 packed FMA) -------------
// out[n,c] = relu( agg[n,:] @ Wl[:,c] + h[n,:] @ Wr[:,c] + b[c] )
// tile 64 rows x 128 cols, BK=16, 256 threads; thread = 4 rows x 8 cols (4 f32x2)
__global__ void __launch_bounds__(256)
gemm_fused(const float* __restrict__ Adata, const float* __restrict__ Hdata,
           const float* __restrict__ Wl, const float* __restrict__ Wr,
           const float* __restrict__ bias, float* __restrict__ out) {
    __shared__ float As[16][68];    // k-major, padded (272B row, 16B aligned)
    __shared__ float Hs[16][68];
    __shared__ float Wls[16][128];  // k-major
    __shared__ float Wrs[16][128];

    int tid = threadIdx.x;
    int tx = tid & 15;   // col block: cols tx*8 .. tx*8+7
    int ty = tid >> 4;   // row block: rows ty*4 .. ty*4+3
    int n0 = blockIdx.x * 64;

    unsigned long long acc2[4][4];
#pragma unroll
    for (int i = 0; i < 4; i++)
#pragma unroll
        for (int j = 0; j < 4; j++) acc2[i][j] = 0ull;

    // loader mapping for A/H tiles: thread -> (row ln, float4 chunk kq)
    int ln = tid >> 2;      // 0..63
    int kq = tid & 3;       // 0..3
    bool inr = (n0 + ln) < Nn;

    for (int k0 = 0; k0 < 128; k0 += 16) {
        // A/H tile load (float4, transpose to k-major in smem)
        float4 av = {0.f, 0.f, 0.f, 0.f}, hv = {0.f, 0.f, 0.f, 0.f};
        if (inr) {
            av = *reinterpret_cast<const float4*>(Adata + (size_t)(n0 + ln) * 128 + k0 + kq * 4);
            hv = *reinterpret_cast<const float4*>(Hdata + (size_t)(n0 + ln) * 128 + k0 + kq * 4);
        }
        As[kq * 4 + 0][ln] = av.x; As[kq * 4 + 1][ln] = av.y;
        As[kq * 4 + 2][ln] = av.z; As[kq * 4 + 3][ln] = av.w;
        Hs[kq * 4 + 0][ln] = hv.x; Hs[kq * 4 + 1][ln] = hv.y;
        Hs[kq * 4 + 2][ln] = hv.z; Hs[kq * 4 + 3][ln] = hv.w;
        // weight tiles (coalesced float4)
#pragma unroll
        for (int it = 0; it < 2; it++) {
            int i = tid + it * 256;          // 0..511 float4 slots
            int r = i >> 5, c4 = i & 31;
            reinterpret_cast<float4*>(&Wls[r][0])[c4] =
                reinterpret_cast<const float4*>(Wl + (size_t)(k0 + r) * 128)[c4];
            reinterpret_cast<float4*>(&Wrs[r][0])[c4] =
                reinterpret_cast<const float4*>(Wr + (size_t)(k0 + r) * 128)[c4];
        }
        __syncthreads();

#pragma unroll
        for (int kk = 0; kk < 16; kk++) {
            float4 a4 = *reinterpret_cast<const float4*>(&As[kk][ty * 4]);
            float4 h4 = *reinterpret_cast<const float4*>(&Hs[kk][ty * 4]);
            ulonglong2 wlA = *reinterpret_cast<const ulonglong2*>(&Wls[kk][tx * 8]);
            ulonglong2 wlB = *reinterpret_cast<const ulonglong2*>(&Wls[kk][tx * 8 + 4]);
            ulonglong2 wrA = *reinterpret_cast<const ulonglong2*>(&Wrs[kk][tx * 8]);
            ulonglong2 wrB = *reinterpret_cast<const ulonglong2*>(&Wrs[kk][tx * 8 + 4]);
            unsigned long long wl2[4] = {wlA.x, wlA.y, wlB.x, wlB.y};
            unsigned long long wr2[4] = {wrA.x, wrA.y, wrB.x, wrB.y};
            unsigned long long a2[4], h2[4];
            a2[0] = pack2(a4.x, a4.x); a2[1] = pack2(a4.y, a4.y);
            a2[2] = pack2(a4.z, a4.z); a2[3] = pack2(a4.w, a4.w);
            h2[0] = pack2(h4.x, h4.x); h2[1] = pack2(h4.y, h4.y);
            h2[2] = pack2(h4.z, h4.z); h2[3] = pack2(h4.w, h4.w);
#pragma unroll
            for (int i = 0; i < 4; i++)
#pragma unroll
                for (int j = 0; j < 4; j++) {
                    acc2[i][j] = fma2(a2[i], wl2[j], acc2[i][j]);
                    acc2[i][j] = fma2(h2[i], wr2[j], acc2[i][j]);
                }
        }
        __syncthreads();
    }

    // epilogue: bias + relu, vectorized stores
    float b[8];
#pragma unroll
    for (int j = 0; j < 8; j++) b[j] = bias[tx * 8 + j];
#pragma unroll
    for (int i = 0; i < 4; i++) {
        int n = n0 + ty * 4 + i;
        if (n < Nn) {
            float v[8];
#pragma unroll
            for (int j = 0; j < 4; j++) unpack2(acc2[i][j], v[2 * j], v[2 * j + 1]);
            float4 o0, o1;
            o0.x = fmaxf(v[0] + b[0], 0.f); o0.y = fmaxf(v[1] + b[1], 0.f);
            o0.z = fmaxf(v[2] + b[2], 0.f); o0.w = fmaxf(v[3] + b[3], 0.f);
            o1.x = fmaxf(v[4] + b[4], 0.f); o1.y = fmaxf(v[5] + b[5], 0.f);
            o1.z = fmaxf(v[6] + b[6], 0.f); o1.w = fmaxf(v[7] + b[7], 0.f);
            *reinterpret_cast<float4*>(out + (size_t)n * 128 + tx * 8) = o0;
            *reinterpret_cast<float4*>(out + (size_t)n * 128 + tx * 8 + 4) = o1;
        }
    }
}

// ---------------- segmented mean pool (batch is sorted) ------------------------
__global__ void segpool_kernel(const float* __restrict__ h,
                               const int* __restrict__ batch) {
    __shared__ int sbeg, send;
    int g = blockIdx.x;
    int j = threadIdx.x;  // 128 threads
    if (j == 0) {
        int lo = 0, hi = Nn;
        while (lo < hi) { int mid = (lo + hi) >> 1; if (batch[mid] < g) lo = mid + 1; else hi = mid; }
        sbeg = lo;
        lo = 0; hi = Nn;
        while (lo < hi) { int mid = (lo + hi) >> 1; if (batch[mid] < g + 1) lo = mid + 1; else hi = mid; }
        send = lo;
    }
    __syncthreads();
    int beg = sbeg, end = send;
    float acc = 0.f;
    int r = beg;
    for (; r + 3 < end; r += 4) {
        acc += h[(size_t)r * 128 + j];
        acc += h[(size_t)(r + 1) * 128 + j];
        acc += h[(size_t)(r + 2) * 128 + j];
        acc += h[(size_t)(r + 3) * 128 + j];
    }
    for (; r < end; r++) acc += h[(size_t)r * 128 + j];
    float c = fmaxf((float)(end - beg), 1.0f);
    g_pool[g * 128 + j] = acc / c;
}

// ---------------- final MLP head ------------------------------------------------
__global__ void mlp_kernel(const float* __restrict__ Wf1,
                           const float* __restrict__ bf1,
                           const float* __restrict__ Wf2,
                           const float* __restrict__ bf2,
                           float* __restrict__ out) {
    __shared__ float gs[128];
    __shared__ float red[128];
    int j = threadIdx.x;
    for (int gi = 0; gi < Gg; gi++) {
        gs[j] = g_pool[gi * 128 + j];
        __syncthreads();
        float acc = bf1[j];
#pragma unroll 8
        for (int k = 0; k < 128; k++) acc += gs[k] * Wf1[k * 128 + j];
        float hid = fmaxf(acc, 0.0f);
        red[j] = hid * Wf2[j];
        __syncthreads();
        for (int s = 64; s > 0; s >>= 1) {
            if (j < s) red[j] += red[j + s];
            __syncthreads();
        }
        if (j == 0) out[gi] = 1.0f / (1.0f + expf(-(red[0] + bf2[0])));
        __syncthreads();
    }
}

// ---------------- launch ---------------------------------------------------------
extern "C" void kernel_launch(void* const* d_in, const int* in_sizes, int n_in,
                              void* d_out, int out_size) {
    const float* x = (const float*)d_in[0];
    const int* el = (const int*)d_in[1];
    const int* batch = (const int*)d_in[2];
    const float *Wl[5], *Wr[5], *bb[5];
    for (int i = 0; i < 5; i++) {
        Wl[i] = (const float*)d_in[3 + 3 * i];
        Wr[i] = (const float*)d_in[4 + 3 * i];
        bb[i] = (const float*)d_in[5 + 3 * i];
    }
    const float* Wf1 = (const float*)d_in[18];
    const float* bf1 = (const float*)d_in[19];
    const float* Wf2 = (const float*)d_in[20];
    const float* bf2 = (const float*)d_in[21];
    float* out = (float*)d_out;

    float *h1, *h2, *agg;
    int* cntn;
    cudaGetSymbolAddress((void**)&h1, g_h1);
    cudaGetSymbolAddress((void**)&h2, g_h2);
    cudaGetSymbolAddress((void**)&agg, g_agg);
    cudaGetSymbolAddress((void**)&cntn, g_cntn);

    // CSR build (once): degree histogram -> scan -> bucket fill
    zero_int_kernel<<<(Nn + 255) / 256, 256>>>(cntn, Nn);
    hist_kernel<<<(Ee + 255) / 256, 256>>>((const int2*)el);
    scan_kernel<<<1, 1024>>>();
    fill_kernel<<<(Ee + 255) / 256, 256>>>((const int2*)el);

    // 5 SAGE layers: gather (no atomics) + fused dual GEMM
    const float* hin = x;
    for (int l = 0; l < 5; l++) {
        gather_kernel<<<(Nn * 32 + 255) / 256, 256>>>(hin);
        float* ho = (l & 1) ? h2 : h1;
        gemm_fused<<<(Nn + 63) / 64, 256>>>(agg, hin, Wl[l], Wr[l], bb[l], ho);
        hin = ho;
    }

    // segmented mean pool (batch sorted) + MLP head
    segpool_kernel<<<Gg, 128>>>(hin, batch);
    mlp_kernel<<<1, 128>>>(Wf1, bf1, Wf2, bf2, out);
}

// round 4
// speedup vs baseline: 2.8636x; 1.4966x over previous
#include <cuda_runtime.h>
#include <math.h>
#include <stdint.h>

#define Nn 50000
#define Ee 800000
#define Hh 128
#define Gg 128
#define NSCAN_BLK 49   // ceil(50000/1024)

// ---------------- scratch (allocation-free: __device__ globals) --------------
__device__ float g_h1[Nn * Hh];
__device__ float g_h2[Nn * Hh];
__device__ float g_agg[Nn * Hh];
__device__ float g_invdeg[Nn];
__device__ float g_pool[Gg * Hh];
__device__ int   g_cntn[Nn];
__device__ int   g_scan[Nn];
__device__ int   g_bsum[NSCAN_BLK];
__device__ int   g_boff[NSCAN_BLK];
__device__ int   g_rowptr[Nn + 1];
__device__ int   g_cursor[Nn];
__device__ int   g_srcidx[Ee];

// ---------------- f32x2 helpers ----------------------------------------------
typedef unsigned long long ull;
__device__ __forceinline__ ull pack2(float lo, float hi) {
    ull r;
    asm("mov.b64 %0, {%1,%2};" : "=l"(r) : "f"(lo), "f"(hi));
    return r;
}
__device__ __forceinline__ ull fma2(ull a, ull b, ull c) {
    ull d;
    asm("fma.rn.f32x2 %0, %1, %2, %3;" : "=l"(d) : "l"(a), "l"(b), "l"(c));
    return d;
}
__device__ __forceinline__ void unpack2(ull v, float& lo, float& hi) {
    lo = __uint_as_float((unsigned)(v & 0xffffffffull));
    hi = __uint_as_float((unsigned)(v >> 32));
}

// ---------------- CSR build ----------------------------------------------------
__global__ void zero_int_kernel(int* __restrict__ p, int n) {
    int i = blockIdx.x * blockDim.x + threadIdx.x;
    if (i < n) p[i] = 0;
}
__global__ void hist_kernel(const int2* __restrict__ el) {
    int e = blockIdx.x * blockDim.x + threadIdx.x;
    if (e < Ee) atomicAdd(&g_cntn[el[e].y], 1);
}
// phase 1: per-block inclusive scan of degree counts
__global__ void scan1_kernel() {
    __shared__ int sh[1024];
    int tid = threadIdx.x;
    int i = blockIdx.x * 1024 + tid;
    int v = (i < Nn) ? g_cntn[i] : 0;
    sh[tid] = v;
    __syncthreads();
    for (int off = 1; off < 1024; off <<= 1) {
        int t = (tid >= off) ? sh[tid - off] : 0;
        __syncthreads();
        sh[tid] += t;
        __syncthreads();
    }
    if (i < Nn) g_scan[i] = sh[tid];
    if (tid == 1023) g_bsum[blockIdx.x] = sh[1023];
}
// phase 2: exclusive scan of block sums (tiny)
__global__ void scan2_kernel() {
    __shared__ int sh[64];
    int tid = threadIdx.x;
    sh[tid] = (tid < NSCAN_BLK) ? g_bsum[tid] : 0;
    __syncthreads();
    for (int off = 1; off < 64; off <<= 1) {
        int t = (tid >= off) ? sh[tid - off] : 0;
        __syncthreads();
        sh[tid] += t;
        __syncthreads();
    }
    if (tid < NSCAN_BLK) g_boff[tid] = sh[tid] - g_bsum[tid];
}
// phase 3: finalize rowptr/cursor/invdeg
__global__ void scan3_kernel() {
    int i = blockIdx.x * blockDim.x + threadIdx.x;
    if (i < Nn) {
        int v = g_cntn[i];
        int excl = g_scan[i] - v + g_boff[i >> 10];
        g_rowptr[i] = excl;
        g_cursor[i] = excl;
        g_invdeg[i] = 1.0f / fmaxf((float)v, 1.0f);
    }
    if (i == 0) g_rowptr[Nn] = Ee;
}
__global__ void fill_kernel(const int2* __restrict__ el) {
    int e = blockIdx.x * blockDim.x + threadIdx.x;
    if (e < Ee) {
        int2 ed = el[e];
        int pos = atomicAdd(&g_cursor[ed.y], 1);
        g_srcidx[pos] = ed.x;
    }
}

// ---------------- neighbor gather: agg[n] = invdeg[n] * sum h[nbrs] ------------
__global__ void __launch_bounds__(256)
gather_kernel(const float* __restrict__ hin) {
    int w = (blockIdx.x * blockDim.x + threadIdx.x) >> 5;
    if (w >= Nn) return;
    int lane = threadIdx.x & 31;
    int beg = g_rowptr[w], end = g_rowptr[w + 1];
    float4 acc = {0.f, 0.f, 0.f, 0.f};
    int i = beg;
    for (; i + 1 < end; i += 2) {
        int s0 = g_srcidx[i];
        int s1 = g_srcidx[i + 1];
        float4 v0 = reinterpret_cast<const float4*>(hin + (size_t)s0 * Hh)[lane];
        float4 v1 = reinterpret_cast<const float4*>(hin + (size_t)s1 * Hh)[lane];
        acc.x += v0.x + v1.x;
        acc.y += v0.y + v1.y;
        acc.z += v0.z + v1.z;
        acc.w += v0.w + v1.w;
    }
    if (i < end) {
        int s0 = g_srcidx[i];
        float4 v0 = reinterpret_cast<const float4*>(hin + (size_t)s0 * Hh)[lane];
        acc.x += v0.x; acc.y += v0.y; acc.z += v0.z; acc.w += v0.w;
    }
    float inv = g_invdeg[w];
    acc.x *= inv; acc.y *= inv; acc.z *= inv; acc.w *= inv;
    reinterpret_cast<float4*>(g_agg + (size_t)w * Hh)[lane] = acc;
}

// ---------------- fused dual GEMM as single K=256, f32x2, double-buffered -------
// out[n,c] = relu( agg[n,:] @ Wl[:,c] + h[n,:] @ Wr[:,c] + b[c] )
// CTA tile 128x128, 256 threads, 8x8 per thread, BK=16, 16 K-stages.
// A-tile stored DUPLICATED in smem: As2[kk][2r]=As2[kk][2r+1]=A[r][kk], so the
// inner loop loads ready-made (a,a) f32x2 splats with zero pack MOVs.
__global__ void __launch_bounds__(256, 2)
gemm_fused(const float* __restrict__ Agg, const float* __restrict__ Hin,
           const float* __restrict__ Wl, const float* __restrict__ Wr,
           const float* __restrict__ bias, float* __restrict__ hout) {
    __shared__ float As2[2][16][256];   // 2 x 16KB (dup pairs, k-major)
    __shared__ float Ws[2][16][128];    // 2 x 8KB  (k-major, as in global)

    int tid = threadIdx.x;
    int tx = tid & 15;      // col block: cols tx*8 .. tx*8+7
    int ty = tid >> 4;      // row block: rows ty*8 .. ty*8+7
    int n0 = blockIdx.x * 128;

    ull acc2[8][4];
#pragma unroll
    for (int i = 0; i < 8; i++)
#pragma unroll
        for (int j = 0; j < 4; j++) acc2[i][j] = 0ull;

    // ---- staging-register loaders -------------------------------------------
    // A tile: 128 rows x 16 k = 512 float4 chunks, 2 per thread
    // chunk c: row = c>>2, kq = c&3 (k offset kq*4)
    // W tile: 16 k-rows x 128 cols = 512 float4 chunks, 2 per thread
    // chunk c: kr = c>>5, c4 = c&31
    float4 ra[2], rw[2];

    auto load_stage = [&](int it) {
        int kbase = it * 16;              // 0..255
        const float* Asrc = (it < 8) ? Agg : Hin;
        const float* Wsrc = (it < 8) ? Wl : Wr;
        int ak = (it < 8) ? kbase : kbase - 128;
#pragma unroll
        for (int rep = 0; rep < 2; rep++) {
            int c = tid + rep * 256;
            int row = c >> 2, kq = c & 3;
            int n = n0 + row; if (n >= Nn) n = Nn - 1;
            ra[rep] = *reinterpret_cast<const float4*>(Asrc + (size_t)n * 128 + ak + kq * 4);
            int kr = c >> 5, c4 = c & 31;
            rw[rep] = *reinterpret_cast<const float4*>(Wsrc + (size_t)(ak + kr) * 128 + c4 * 4);
        }
    };
    auto store_stage = [&](int buf) {
#pragma unroll
        for (int rep = 0; rep < 2; rep++) {
            int c = tid + rep * 256;
            int row = c >> 2, kq = c & 3;
            float v[4] = {ra[rep].x, ra[rep].y, ra[rep].z, ra[rep].w};
#pragma unroll
            for (int j = 0; j < 4; j++)
                *reinterpret_cast<ull*>(&As2[buf][kq * 4 + j][2 * row]) = pack2(v[j], v[j]);
            int kr = c >> 5, c4 = c & 31;
            *reinterpret_cast<float4*>(&Ws[buf][kr][c4 * 4]) = rw[rep];
        }
    };

    // prologue
    load_stage(0);
    store_stage(0);
    __syncthreads();

    for (int it = 0; it < 16; it++) {
        int buf = it & 1;
        if (it < 15) load_stage(it + 1);   // LDG in flight during compute

#pragma unroll
        for (int kk = 0; kk < 16; kk++) {
            ulonglong2 q0 = *reinterpret_cast<const ulonglong2*>(&As2[buf][kk][ty * 16]);
            ulonglong2 q1 = *reinterpret_cast<const ulonglong2*>(&As2[buf][kk][ty * 16 + 4]);
            ulonglong2 q2 = *reinterpret_cast<const ulonglong2*>(&As2[buf][kk][ty * 16 + 8]);
            ulonglong2 q3 = *reinterpret_cast<const ulonglong2*>(&As2[buf][kk][ty * 16 + 12]);
            ulonglong2 w0 = *reinterpret_cast<const ulonglong2*>(&Ws[buf][kk][tx * 8]);
            ulonglong2 w1 = *reinterpret_cast<const ulonglong2*>(&Ws[buf][kk][tx * 8 + 4]);
            ull a2[8] = {q0.x, q0.y, q1.x, q1.y, q2.x, q2.y, q3.x, q3.y};
            ull w2[4] = {w0.x, w0.y, w1.x, w1.y};
#pragma unroll
            for (int i = 0; i < 8; i++)
#pragma unroll
                for (int j = 0; j < 4; j++)
                    acc2[i][j] = fma2(a2[i], w2[j], acc2[i][j]);
        }
        __syncthreads();
        if (it < 15) {
            store_stage(1 - buf);
            __syncthreads();
        }
    }

    // epilogue: bias + relu, float4 stores
    float b[8];
#pragma unroll
    for (int j = 0; j < 8; j++) b[j] = __ldg(bias + tx * 8 + j);
#pragma unroll
    for (int i = 0; i < 8; i++) {
        int n = n0 + ty * 8 + i;
        if (n < Nn) {
            float v[8];
#pragma unroll
            for (int j = 0; j < 4; j++) unpack2(acc2[i][j], v[2 * j], v[2 * j + 1]);
            float4 o0, o1;
            o0.x = fmaxf(v[0] + b[0], 0.f); o0.y = fmaxf(v[1] + b[1], 0.f);
            o0.z = fmaxf(v[2] + b[2], 0.f); o0.w = fmaxf(v[3] + b[3], 0.f);
            o1.x = fmaxf(v[4] + b[4], 0.f); o1.y = fmaxf(v[5] + b[5], 0.f);
            o1.z = fmaxf(v[6] + b[6], 0.f); o1.w = fmaxf(v[7] + b[7], 0.f);
            *reinterpret_cast<float4*>(hout + (size_t)n * 128 + tx * 8) = o0;
            *reinterpret_cast<float4*>(hout + (size_t)n * 128 + tx * 8 + 4) = o1;
        }
    }
}

// ---------------- segmented mean pool (batch is sorted) -------------------------
__global__ void segpool_kernel(const float* __restrict__ h,
                               const int* __restrict__ batch) {
    __shared__ int sbeg, send;
    int g = blockIdx.x;
    int j = threadIdx.x;
    if (j == 0) {
        int lo = 0, hi = Nn;
        while (lo < hi) { int mid = (lo + hi) >> 1; if (batch[mid] < g) lo = mid + 1; else hi = mid; }
        sbeg = lo;
        lo = 0; hi = Nn;
        while (lo < hi) { int mid = (lo + hi) >> 1; if (batch[mid] < g + 1) lo = mid + 1; else hi = mid; }
        send = lo;
    }
    __syncthreads();
    int beg = sbeg, end = send;
    float acc = 0.f;
    int r = beg;
    for (; r + 3 < end; r += 4) {
        acc += h[(size_t)r * 128 + j];
        acc += h[(size_t)(r + 1) * 128 + j];
        acc += h[(size_t)(r + 2) * 128 + j];
        acc += h[(size_t)(r + 3) * 128 + j];
    }
    for (; r < end; r++) acc += h[(size_t)r * 128 + j];
    float c = fmaxf((float)(end - beg), 1.0f);
    g_pool[g * 128 + j] = acc / c;
}

// ---------------- final MLP head: one block per graph ---------------------------
__global__ void mlp_kernel(const float* __restrict__ Wf1,
                           const float* __restrict__ bf1,
                           const float* __restrict__ Wf2,
                           const float* __restrict__ bf2,
                           float* __restrict__ out) {
    __shared__ float gs[128];
    __shared__ float red[128];
    int gi = blockIdx.x;
    int j = threadIdx.x;
    gs[j] = g_pool[gi * 128 + j];
    __syncthreads();
    float acc = bf1[j];
#pragma unroll 8
    for (int k = 0; k < 128; k++) acc += gs[k] * Wf1[k * 128 + j];
    float hid = fmaxf(acc, 0.0f);
    red[j] = hid * Wf2[j];
    __syncthreads();
    for (int s = 64; s > 0; s >>= 1) {
        if (j < s) red[j] += red[j + s];
        __syncthreads();
    }
    if (j == 0) out[gi] = 1.0f / (1.0f + expf(-(red[0] + bf2[0])));
}

// ---------------- launch ----------------------------------------------------------
extern "C" void kernel_launch(void* const* d_in, const int* in_sizes, int n_in,
                              void* d_out, int out_size) {
    const float* x = (const float*)d_in[0];
    const int* el = (const int*)d_in[1];
    const int* batch = (const int*)d_in[2];
    const float *Wl[5], *Wr[5], *bb[5];
    for (int i = 0; i < 5; i++) {
        Wl[i] = (const float*)d_in[3 + 3 * i];
        Wr[i] = (const float*)d_in[4 + 3 * i];
        bb[i] = (const float*)d_in[5 + 3 * i];
    }
    const float* Wf1 = (const float*)d_in[18];
    const float* bf1 = (const float*)d_in[19];
    const float* Wf2 = (const float*)d_in[20];
    const float* bf2 = (const float*)d_in[21];
    float* out = (float*)d_out;

    float *h1, *h2, *agg;
    int* cntn;
    cudaGetSymbolAddress((void**)&h1, g_h1);
    cudaGetSymbolAddress((void**)&h2, g_h2);
    cudaGetSymbolAddress((void**)&agg, g_agg);
    cudaGetSymbolAddress((void**)&cntn, g_cntn);

    // CSR build: histogram -> multi-block scan -> bucket fill
    zero_int_kernel<<<(Nn + 255) / 256, 256>>>(cntn, Nn);
    hist_kernel<<<(Ee + 255) / 256, 256>>>((const int2*)el);
    scan1_kernel<<<NSCAN_BLK, 1024>>>();
    scan2_kernel<<<1, 64>>>();
    scan3_kernel<<<(Nn + 255) / 256, 256>>>();
    fill_kernel<<<(Ee + 255) / 256, 256>>>((const int2*)el);

    // 5 SAGE layers: gather (no atomics) + fused single-K GEMM
    const float* hin = x;
    const int ngrid = (Nn + 127) / 128;
    for (int l = 0; l < 5; l++) {
        gather_kernel<<<(Nn * 32 + 255) / 256, 256>>>(hin);
        float* ho = (l & 1) ? h2 : h1;
        gemm_fused<<<ngrid, 256>>>(agg, hin, Wl[l], Wr[l], bb[l], ho);
        hin = ho;
    }

    // segmented mean pool + parallel MLP head
    segpool_kernel<<<Gg, 128>>>(hin, batch);
    mlp_kernel<<<Gg, 128>>>(Wf1, bf1, Wf2, bf2, out);
}

// round 5
// speedup vs baseline: 2.9945x; 1.0457x over previous
#include <cuda_runtime.h>
#include <cuda_fp16.h>
#include <math.h>
#include <stdint.h>

#define Nn 50000
#define Ee 800000
#define Hh 128
#define Gg 128
#define NSCAN_BLK 49   // ceil(50000/1024)
#define NG_GEMM 391    // ceil(50000/128)

// ---------------- scratch (allocation-free: __device__ globals) --------------
__device__ float  g_h1[Nn * Hh];
__device__ float  g_h2[Nn * Hh];
__device__ float  g_tmp[Nn * Hh];
__device__ float  g_agg[Nn * Hh];
__device__ __half g_hh[Nn * Hh];     // fp16 shadow of current h (gather operand)
__device__ float  g_invdeg[Nn];
__device__ float  g_pool[Gg * Hh];
__device__ int    g_cntn[Nn];
__device__ int    g_scan[Nn];
__device__ int    g_bsum[NSCAN_BLK];
__device__ int    g_rowptr[Nn + 1];
__device__ int    g_cursor[Nn];
__device__ int    g_srcidx[Ee];

// ---------------- f32x2 helpers ----------------------------------------------
typedef unsigned long long ull;
__device__ __forceinline__ ull pack2(float lo, float hi) {
    ull r;
    asm("mov.b64 %0, {%1,%2};" : "=l"(r) : "f"(lo), "f"(hi));
    return r;
}
__device__ __forceinline__ ull fma2(ull a, ull b, ull c) {
    ull d;
    asm("fma.rn.f32x2 %0, %1, %2, %3;" : "=l"(d) : "l"(a), "l"(b), "l"(c));
    return d;
}
__device__ __forceinline__ void unpack2(ull v, float& lo, float& hi) {
    lo = __uint_as_float((unsigned)(v & 0xffffffffull));
    hi = __uint_as_float((unsigned)(v >> 32));
}

// ---------------- CSR build ----------------------------------------------------
__global__ void zero_int_kernel(int* __restrict__ p, int n) {
    int i = blockIdx.x * blockDim.x + threadIdx.x;
    if (i < n) p[i] = 0;
}
__global__ void hist_kernel(const int2* __restrict__ el) {
    int e = blockIdx.x * blockDim.x + threadIdx.x;
    if (e < Ee) atomicAdd(&g_cntn[el[e].y], 1);
}
// per-block inclusive scan of degree counts
__global__ void scan1_kernel() {
    __shared__ int sh[1024];
    int tid = threadIdx.x;
    int i = blockIdx.x * 1024 + tid;
    int v = (i < Nn) ? g_cntn[i] : 0;
    sh[tid] = v;
    __syncthreads();
    for (int off = 1; off < 1024; off <<= 1) {
        int t = (tid >= off) ? sh[tid - off] : 0;
        __syncthreads();
        sh[tid] += t;
        __syncthreads();
    }
    if (i < Nn) g_scan[i] = sh[tid];
    if (tid == 1023) g_bsum[blockIdx.x] = sh[1023];
}
// finalize rowptr/cursor/invdeg; block-offset computed inline in smem
__global__ void scan3_kernel() {
    __shared__ int soff[NSCAN_BLK + 1];
    int tid = threadIdx.x;
    if (tid == 0) {
        int run = 0;
        for (int b = 0; b < NSCAN_BLK; b++) { soff[b] = run; run += g_bsum[b]; }
    }
    __syncthreads();
    int i = blockIdx.x * blockDim.x + tid;
    if (i < Nn) {
        int v = g_cntn[i];
        int excl = g_scan[i] - v + soff[i >> 10];
        g_rowptr[i] = excl;
        g_cursor[i] = excl;
        g_invdeg[i] = 1.0f / fmaxf((float)v, 1.0f);
    }
    if (i == 0) g_rowptr[Nn] = Ee;
}
__global__ void fill_kernel(const int2* __restrict__ el) {
    int e = blockIdx.x * blockDim.x + threadIdx.x;
    if (e < Ee) {
        int2 ed = el[e];
        int pos = atomicAdd(&g_cursor[ed.y], 1);
        g_srcidx[pos] = ed.x;
    }
}

// ---------------- x -> fp16 shadow ------------------------------------------------
__global__ void xhalf_kernel(const float* __restrict__ x) {
    int i = blockIdx.x * blockDim.x + threadIdx.x;   // over pairs
    if (i < Nn * Hh / 2) {
        float2 v = reinterpret_cast<const float2*>(x)[i];
        reinterpret_cast<__half2*>(g_hh)[i] = __floats2half2_rn(v.x, v.y);
    }
}

// ---------------- neighbor gather (fp16 rows, fp32 accumulate) --------------------
// one warp per node; lane handles 4 halves (8B) of the 256B row.
__device__ __forceinline__ void acc_add(float4& a, uint2 v) {
    __half2 h0 = *reinterpret_cast<__half2*>(&v.x);
    __half2 h1 = *reinterpret_cast<__half2*>(&v.y);
    float2 f0 = __half22float2(h0);
    float2 f1 = __half22float2(h1);
    a.x += f0.x; a.y += f0.y; a.z += f1.x; a.w += f1.y;
}
__global__ void __launch_bounds__(256)
gather_kernel(const __half* __restrict__ hh) {
    int w = (blockIdx.x * blockDim.x + threadIdx.x) >> 5;
    if (w >= Nn) return;
    int lane = threadIdx.x & 31;
    int beg = g_rowptr[w], end = g_rowptr[w + 1];
    float4 acc = {0.f, 0.f, 0.f, 0.f};
    int i = beg;
    for (; i + 3 < end; i += 4) {
        int s0 = g_srcidx[i];
        int s1 = g_srcidx[i + 1];
        int s2 = g_srcidx[i + 2];
        int s3 = g_srcidx[i + 3];
        uint2 v0 = reinterpret_cast<const uint2*>(hh + (size_t)s0 * Hh)[lane];
        uint2 v1 = reinterpret_cast<const uint2*>(hh + (size_t)s1 * Hh)[lane];
        uint2 v2 = reinterpret_cast<const uint2*>(hh + (size_t)s2 * Hh)[lane];
        uint2 v3 = reinterpret_cast<const uint2*>(hh + (size_t)s3 * Hh)[lane];
        acc_add(acc, v0); acc_add(acc, v1); acc_add(acc, v2); acc_add(acc, v3);
    }
    for (; i < end; i++) {
        int s0 = g_srcidx[i];
        uint2 v0 = reinterpret_cast<const uint2*>(hh + (size_t)s0 * Hh)[lane];
        acc_add(acc, v0);
    }
    float inv = g_invdeg[w];
    acc.x *= inv; acc.y *= inv; acc.z *= inv; acc.w *= inv;
    reinterpret_cast<float4*>(g_agg + (size_t)w * Hh)[lane] = acc;
}

// ---------------- K=128 GEMM, f32x2, double-buffered ------------------------------
// fuse=0: Cout = A@W
// fuse=1: Cout = relu(A@W + Cin + bias); also writes fp16 shadow Chalf
__global__ void __launch_bounds__(256, 2)
gemm_k128(const float* __restrict__ A, const float* __restrict__ W,
          const float* __restrict__ Cin, const float* __restrict__ bias,
          float* __restrict__ Cout, __half* __restrict__ Chalf, int fuse) {
    __shared__ float As2[2][16][256];   // duplicated (a,a) pairs, k-major
    __shared__ float Ws[2][16][128];

    int tid = threadIdx.x;
    int tx = tid & 15;      // cols tx*8 .. tx*8+7
    int ty = tid >> 4;      // rows ty*8 .. ty*8+7
    int n0 = blockIdx.x * 128;

    ull acc2[8][4];
#pragma unroll
    for (int i = 0; i < 8; i++)
#pragma unroll
        for (int j = 0; j < 4; j++) acc2[i][j] = 0ull;

    float4 ra[2], rw[2];
    auto load_stage = [&](int it) {
        int kbase = it * 16;
#pragma unroll
        for (int rep = 0; rep < 2; rep++) {
            int c = tid + rep * 256;
            int row = c >> 2, kq = c & 3;
            int n = n0 + row; if (n >= Nn) n = Nn - 1;
            ra[rep] = *reinterpret_cast<const float4*>(A + (size_t)n * 128 + kbase + kq * 4);
            int kr = c >> 5, c4 = c & 31;
            rw[rep] = *reinterpret_cast<const float4*>(W + (size_t)(kbase + kr) * 128 + c4 * 4);
        }
    };
    auto store_stage = [&](int buf) {
#pragma unroll
        for (int rep = 0; rep < 2; rep++) {
            int c = tid + rep * 256;
            int row = c >> 2, kq = c & 3;
            float v[4] = {ra[rep].x, ra[rep].y, ra[rep].z, ra[rep].w};
#pragma unroll
            for (int j = 0; j < 4; j++)
                *reinterpret_cast<ull*>(&As2[buf][kq * 4 + j][2 * row]) = pack2(v[j], v[j]);
            int kr = c >> 5, c4 = c & 31;
            *reinterpret_cast<float4*>(&Ws[buf][kr][c4 * 4]) = rw[rep];
        }
    };

    load_stage(0);
    store_stage(0);
    __syncthreads();

    for (int it = 0; it < 8; it++) {
        int buf = it & 1;
        if (it < 7) load_stage(it + 1);

#pragma unroll
        for (int kk = 0; kk < 16; kk++) {
            ulonglong2 q0 = *reinterpret_cast<const ulonglong2*>(&As2[buf][kk][ty * 16]);
            ulonglong2 q1 = *reinterpret_cast<const ulonglong2*>(&As2[buf][kk][ty * 16 + 4]);
            ulonglong2 q2 = *reinterpret_cast<const ulonglong2*>(&As2[buf][kk][ty * 16 + 8]);
            ulonglong2 q3 = *reinterpret_cast<const ulonglong2*>(&As2[buf][kk][ty * 16 + 12]);
            ulonglong2 w0 = *reinterpret_cast<const ulonglong2*>(&Ws[buf][kk][tx * 8]);
            ulonglong2 w1 = *reinterpret_cast<const ulonglong2*>(&Ws[buf][kk][tx * 8 + 4]);
            ull a2[8] = {q0.x, q0.y, q1.x, q1.y, q2.x, q2.y, q3.x, q3.y};
            ull w2[4] = {w0.x, w0.y, w1.x, w1.y};
#pragma unroll
            for (int i = 0; i < 8; i++)
#pragma unroll
                for (int j = 0; j < 4; j++)
                    acc2[i][j] = fma2(a2[i], w2[j], acc2[i][j]);
        }
        __syncthreads();
        if (it < 7) {
            store_stage(1 - buf);
            __syncthreads();
        }
    }

    if (fuse) {
        float b[8];
#pragma unroll
        for (int j = 0; j < 8; j++) b[j] = __ldg(bias + tx * 8 + j);
#pragma unroll
        for (int i = 0; i < 8; i++) {
            int n = n0 + ty * 8 + i;
            if (n < Nn) {
                float v[8];
#pragma unroll
                for (int j = 0; j < 4; j++) unpack2(acc2[i][j], v[2 * j], v[2 * j + 1]);
                float4 c0 = *reinterpret_cast<const float4*>(Cin + (size_t)n * 128 + tx * 8);
                float4 c1 = *reinterpret_cast<const float4*>(Cin + (size_t)n * 128 + tx * 8 + 4);
                float4 o0, o1;
                o0.x = fmaxf(v[0] + c0.x + b[0], 0.f);
                o0.y = fmaxf(v[1] + c0.y + b[1], 0.f);
                o0.z = fmaxf(v[2] + c0.z + b[2], 0.f);
                o0.w = fmaxf(v[3] + c0.w + b[3], 0.f);
                o1.x = fmaxf(v[4] + c1.x + b[4], 0.f);
                o1.y = fmaxf(v[5] + c1.y + b[5], 0.f);
                o1.z = fmaxf(v[6] + c1.z + b[6], 0.f);
                o1.w = fmaxf(v[7] + c1.w + b[7], 0.f);
                *reinterpret_cast<float4*>(Cout + (size_t)n * 128 + tx * 8) = o0;
                *reinterpret_cast<float4*>(Cout + (size_t)n * 128 + tx * 8 + 4) = o1;
                __half2 p0 = __floats2half2_rn(o0.x, o0.y);
                __half2 p1 = __floats2half2_rn(o0.z, o0.w);
                __half2 p2 = __floats2half2_rn(o1.x, o1.y);
                __half2 p3 = __floats2half2_rn(o1.z, o1.w);
                uint4 u;
                u.x = *reinterpret_cast<uint32_t*>(&p0);
                u.y = *reinterpret_cast<uint32_t*>(&p1);
                u.z = *reinterpret_cast<uint32_t*>(&p2);
                u.w = *reinterpret_cast<uint32_t*>(&p3);
                *reinterpret_cast<uint4*>(Chalf + (size_t)n * 128 + tx * 8) = u;
            }
        }
    } else {
#pragma unroll
        for (int i = 0; i < 8; i++) {
            int n = n0 + ty * 8 + i;
            if (n < Nn) {
                float v[8];
#pragma unroll
                for (int j = 0; j < 4; j++) unpack2(acc2[i][j], v[2 * j], v[2 * j + 1]);
                float4 o0 = {v[0], v[1], v[2], v[3]};
                float4 o1 = {v[4], v[5], v[6], v[7]};
                *reinterpret_cast<float4*>(Cout + (size_t)n * 128 + tx * 8) = o0;
                *reinterpret_cast<float4*>(Cout + (size_t)n * 128 + tx * 8 + 4) = o1;
            }
        }
    }
}

// ---------------- segmented mean pool (batch is sorted) ---------------------------
__global__ void segpool_kernel(const float* __restrict__ h,
                               const int* __restrict__ batch) {
    __shared__ int sbeg, send;
    int g = blockIdx.x;
    int j = threadIdx.x;
    if (j == 0) {
        int lo = 0, hi = Nn;
        while (lo < hi) { int mid = (lo + hi) >> 1; if (batch[mid] < g) lo = mid + 1; else hi = mid; }
        sbeg = lo;
        lo = 0; hi = Nn;
        while (lo < hi) { int mid = (lo + hi) >> 1; if (batch[mid] < g + 1) lo = mid + 1; else hi = mid; }
        send = lo;
    }
    __syncthreads();
    int beg = sbeg, end = send;
    float acc = 0.f;
    int r = beg;
    for (; r + 3 < end; r += 4) {
        acc += h[(size_t)r * 128 + j];
        acc += h[(size_t)(r + 1) * 128 + j];
        acc += h[(size_t)(r + 2) * 128 + j];
        acc += h[(size_t)(r + 3) * 128 + j];
    }
    for (; r < end; r++) acc += h[(size_t)r * 128 + j];
    float c = fmaxf((float)(end - beg), 1.0f);
    g_pool[g * 128 + j] = acc / c;
}

// ---------------- final MLP head: one block per graph ------------------------------
__global__ void mlp_kernel(const float* __restrict__ Wf1,
                           const float* __restrict__ bf1,
                           const float* __restrict__ Wf2,
                           const float* __restrict__ bf2,
                           float* __restrict__ out) {
    __shared__ float gs[128];
    __shared__ float red[128];
    int gi = blockIdx.x;
    int j = threadIdx.x;
    gs[j] = g_pool[gi * 128 + j];
    __syncthreads();
    float acc = bf1[j];
#pragma unroll 8
    for (int k = 0; k < 128; k++) acc += gs[k] * Wf1[k * 128 + j];
    float hid = fmaxf(acc, 0.0f);
    red[j] = hid * Wf2[j];
    __syncthreads();
    for (int s = 64; s > 0; s >>= 1) {
        if (j < s) red[j] += red[j + s];
        __syncthreads();
    }
    if (j == 0) out[gi] = 1.0f / (1.0f + expf(-(red[0] + bf2[0])));
}

// ---------------- launch --------------------------------------------------------------
extern "C" void kernel_launch(void* const* d_in, const int* in_sizes, int n_in,
                              void* d_out, int out_size) {
    const float* x = (const float*)d_in[0];
    const int* el = (const int*)d_in[1];
    const int* batch = (const int*)d_in[2];
    const float *Wl[5], *Wr[5], *bb[5];
    for (int i = 0; i < 5; i++) {
        Wl[i] = (const float*)d_in[3 + 3 * i];
        Wr[i] = (const float*)d_in[4 + 3 * i];
        bb[i] = (const float*)d_in[5 + 3 * i];
    }
    const float* Wf1 = (const float*)d_in[18];
    const float* bf1 = (const float*)d_in[19];
    const float* Wf2 = (const float*)d_in[20];
    const float* bf2 = (const float*)d_in[21];
    float* out = (float*)d_out;

    float *h1, *h2, *tmp, *agg;
    __half* hh;
    int* cntn;
    cudaGetSymbolAddress((void**)&h1, g_h1);
    cudaGetSymbolAddress((void**)&h2, g_h2);
    cudaGetSymbolAddress((void**)&tmp, g_tmp);
    cudaGetSymbolAddress((void**)&agg, g_agg);
    cudaGetSymbolAddress((void**)&hh, g_hh);
    cudaGetSymbolAddress((void**)&cntn, g_cntn);

    // side stream + fork/join events (created once; graph-capture-legal pattern)
    static cudaStream_t s1 = nullptr;
    static cudaEvent_t evF[5], evJ[5];
    if (!s1) {
        cudaStreamCreateWithFlags(&s1, cudaStreamNonBlocking);
        for (int i = 0; i < 5; i++) {
            cudaEventCreateWithFlags(&evF[i], cudaEventDisableTiming);
            cudaEventCreateWithFlags(&evJ[i], cudaEventDisableTiming);
        }
    }

    // fork: layer-1 gemm1 (x@Wr1) depends only on inputs -> overlaps CSR build
    cudaEventRecord(evF[0], 0);
    cudaStreamWaitEvent(s1, evF[0], 0);
    gemm_k128<<<NG_GEMM, 256, 0, s1>>>(x, Wr[0], nullptr, nullptr, tmp, nullptr, 0);

    // CSR build + x fp16 shadow on main stream
    zero_int_kernel<<<(Nn + 255) / 256, 256>>>(cntn, Nn);
    hist_kernel<<<(Ee + 255) / 256, 256>>>((const int2*)el);
    scan1_kernel<<<NSCAN_BLK, 1024>>>();
    scan3_kernel<<<(Nn + 255) / 256, 256>>>();
    fill_kernel<<<(Ee + 255) / 256, 256>>>((const int2*)el);
    xhalf_kernel<<<(Nn * Hh / 2 + 255) / 256, 256>>>(x);

    // 5 layers: [gather || gemm1] -> join -> gemm2
    for (int l = 0; l < 5; l++) {
        gather_kernel<<<(Nn * 32 + 255) / 256, 256>>>(hh);
        cudaEventRecord(evJ[l], s1);
        cudaStreamWaitEvent(0, evJ[l], 0);
        float* ho = (l & 1) ? h2 : h1;
        gemm_k128<<<NG_GEMM, 256>>>(agg, Wl[l], tmp, bb[l], ho, hh, 1);
        if (l < 4) {
            cudaEventRecord(evF[l + 1], 0);
            cudaStreamWaitEvent(s1, evF[l + 1], 0);
            gemm_k128<<<NG_GEMM, 256, 0, s1>>>(ho, Wr[l + 1], nullptr, nullptr, tmp, nullptr, 0);
        }
    }

    // segmented mean pool + parallel MLP head
    const float* hfin = h1;  // layer 5 (l=4) wrote h1
    segpool_kernel<<<Gg, 128>>>(hfin, batch);
    mlp_kernel<<<Gg, 128>>>(Wf1, bf1, Wf2, bf2, out);
}

// round 6
// speedup vs baseline: 7.7845x; 2.5996x over previous
#include <cuda_runtime.h>
#include <cuda_fp16.h>
#include <math.h>
#include <stdint.h>

#define Nn 50000
#define Ee 800000
#define Hh 128
#define Gg 128
#define NSCAN_BLK 49        // ceil(50000/1024)
#define NG_GEMM 391         // ceil(50000/128)
#define NWCAT (5 * 256 * 128)

// ---------------- scratch (allocation-free: __device__ globals) --------------
__device__ __half g_hh[Nn * Hh];      // fp16 h (current layer activations)
__device__ __half g_aggh[Nn * Hh];    // fp16 agg
__device__ __half g_wcat[NWCAT];      // fp16 [layer][k=256][n=128]
__device__ float  g_invdeg[Nn];
__device__ float  g_pool[Gg * Hh];
__device__ int    g_cntn[Nn];
__device__ int    g_scan[Nn];
__device__ int    g_bsum[NSCAN_BLK];
__device__ int    g_rowptr[Nn + 1];
__device__ int    g_cursor[Nn];
__device__ int    g_srcidx[Ee];

struct WPtrs { const float* p[10]; };

// ---------------- PTX wrappers -------------------------------------------------
__device__ __forceinline__ uint32_t smem_u32(const void* p) {
    uint32_t a;
    asm("{ .reg .u64 t; cvta.to.shared.u64 t, %1; cvt.u32.u64 %0, t; }"
        : "=r"(a) : "l"(p));
    return a;
}
__device__ __forceinline__ void ldsm_x4(uint32_t& r0, uint32_t& r1,
                                        uint32_t& r2, uint32_t& r3, uint32_t addr) {
    asm volatile("ldmatrix.sync.aligned.m8n8.x4.shared.b16 {%0,%1,%2,%3}, [%4];"
                 : "=r"(r0), "=r"(r1), "=r"(r2), "=r"(r3) : "r"(addr));
}
__device__ __forceinline__ void ldsm_x4t(uint32_t& r0, uint32_t& r1,
                                         uint32_t& r2, uint32_t& r3, uint32_t addr) {
    asm volatile("ldmatrix.sync.aligned.m8n8.x4.trans.shared.b16 {%0,%1,%2,%3}, [%4];"
                 : "=r"(r0), "=r"(r1), "=r"(r2), "=r"(r3) : "r"(addr));
}
__device__ __forceinline__ void mma16816(float* d, const uint32_t* a,
                                         uint32_t b0, uint32_t b1) {
    asm volatile(
        "mma.sync.aligned.m16n8k16.row.col.f32.f16.f16.f32 "
        "{%0,%1,%2,%3}, {%4,%5,%6,%7}, {%8,%9}, {%0,%1,%2,%3};"
        : "+f"(d[0]), "+f"(d[1]), "+f"(d[2]), "+f"(d[3])
        : "r"(a[0]), "r"(a[1]), "r"(a[2]), "r"(a[3]), "r"(b0), "r"(b1));
}

// ---------------- fused prep: zero cntn + x->fp16 + Wcat fp16 -------------------
__global__ void prep_kernel(const float* __restrict__ x, WPtrs wp) {
    int i = blockIdx.x * blockDim.x + threadIdx.x;
    if (i < Nn * Hh / 2) {
        float2 v = reinterpret_cast<const float2*>(x)[i];
        reinterpret_cast<__half2*>(g_hh)[i] = __floats2half2_rn(v.x, v.y);
    }
    if (i < Nn) g_cntn[i] = 0;
    if (i < NWCAT) {
        int l = i >> 15;             // / 32768
        int rem = i & 32767;
        int k = rem >> 7, n = rem & 127;
        const float* W = (k < 128) ? wp.p[2 * l] : wp.p[2 * l + 1];
        g_wcat[i] = __float2half_rn(W[(k & 127) * 128 + n]);
    }
}

// ---------------- CSR build ------------------------------------------------------
__global__ void hist_kernel(const int2* __restrict__ el) {
    int e = blockIdx.x * blockDim.x + threadIdx.x;
    if (e < Ee) atomicAdd(&g_cntn[el[e].y], 1);
}
__global__ void scan1_kernel() {
    __shared__ int sh[1024];
    int tid = threadIdx.x;
    int i = blockIdx.x * 1024 + tid;
    int v = (i < Nn) ? g_cntn[i] : 0;
    sh[tid] = v;
    __syncthreads();
    for (int off = 1; off < 1024; off <<= 1) {
        int t = (tid >= off) ? sh[tid - off] : 0;
        __syncthreads();
        sh[tid] += t;
        __syncthreads();
    }
    if (i < Nn) g_scan[i] = sh[tid];
    if (tid == 1023) g_bsum[blockIdx.x] = sh[1023];
}
__global__ void scan3_kernel() {
    __shared__ int soff[NSCAN_BLK + 1];
    int tid = threadIdx.x;
    if (tid == 0) {
        int run = 0;
        for (int b = 0; b < NSCAN_BLK; b++) { soff[b] = run; run += g_bsum[b]; }
    }
    __syncthreads();
    int i = blockIdx.x * blockDim.x + tid;
    if (i < Nn) {
        int v = g_cntn[i];
        int excl = g_scan[i] - v + soff[i >> 10];
        g_rowptr[i] = excl;
        g_cursor[i] = excl;
        g_invdeg[i] = 1.0f / fmaxf((float)v, 1.0f);
    }
    if (i == 0) g_rowptr[Nn] = Ee;
}
__global__ void fill_kernel(const int2* __restrict__ el) {
    int e = blockIdx.x * blockDim.x + threadIdx.x;
    if (e < Ee) {
        int2 ed = el[e];
        int pos = atomicAdd(&g_cursor[ed.y], 1);
        g_srcidx[pos] = ed.x;
    }
}

// ---------------- neighbor gather (fp16 rows, fp32 acc, fp16 out) ----------------
__device__ __forceinline__ void acc_add(float4& a, uint2 v) {
    __half2 h0 = *reinterpret_cast<__half2*>(&v.x);
    __half2 h1 = *reinterpret_cast<__half2*>(&v.y);
    float2 f0 = __half22float2(h0);
    float2 f1 = __half22float2(h1);
    a.x += f0.x; a.y += f0.y; a.z += f1.x; a.w += f1.y;
}
__global__ void __launch_bounds__(256)
gather_kernel(const __half* __restrict__ hh) {
    int w = (blockIdx.x * blockDim.x + threadIdx.x) >> 5;
    if (w >= Nn) return;
    int lane = threadIdx.x & 31;
    int beg = g_rowptr[w], end = g_rowptr[w + 1];
    float4 acc = {0.f, 0.f, 0.f, 0.f};
    int i = beg;
    for (; i + 3 < end; i += 4) {
        int s0 = g_srcidx[i];
        int s1 = g_srcidx[i + 1];
        int s2 = g_srcidx[i + 2];
        int s3 = g_srcidx[i + 3];
        uint2 v0 = reinterpret_cast<const uint2*>(hh + (size_t)s0 * Hh)[lane];
        uint2 v1 = reinterpret_cast<const uint2*>(hh + (size_t)s1 * Hh)[lane];
        uint2 v2 = reinterpret_cast<const uint2*>(hh + (size_t)s2 * Hh)[lane];
        uint2 v3 = reinterpret_cast<const uint2*>(hh + (size_t)s3 * Hh)[lane];
        acc_add(acc, v0); acc_add(acc, v1); acc_add(acc, v2); acc_add(acc, v3);
    }
    for (; i < end; i++) {
        int s0 = g_srcidx[i];
        uint2 v0 = reinterpret_cast<const uint2*>(hh + (size_t)s0 * Hh)[lane];
        acc_add(acc, v0);
    }
    float inv = g_invdeg[w];
    __half2 p0 = __floats2half2_rn(acc.x * inv, acc.y * inv);
    __half2 p1 = __floats2half2_rn(acc.z * inv, acc.w * inv);
    uint2 u;
    u.x = *reinterpret_cast<uint32_t*>(&p0);
    u.y = *reinterpret_cast<uint32_t*>(&p1);
    reinterpret_cast<uint2*>(g_aggh + (size_t)w * Hh)[lane] = u;
}

// ---------------- tensor-core GEMM: h' = relu([agg|h] @ Wcat + b) ----------------
// K=256 in 2 stages of 128. CTA 128x128, 8 warps (4 row x 2 col), warp 32x64.
// mma.sync.m16n8k16 fp16->fp32. In-place fp16 output into hh.
#define APITCH 136   // 128 + 8 halves pad -> 272B rows, conflict-free ldmatrix
__global__ void __launch_bounds__(256, 2)
gemm_mma(const __half* __restrict__ Ah,      // agg fp16   (K 0..127)
         const __half* __restrict__ Hf,      // h   fp16   (K 128..255)
         const __half* __restrict__ Wc,      // [256][128] fp16 layer slice
         const float* __restrict__ bias,
         __half* __restrict__ Hout) {
    extern __shared__ __half smem[];
    __half* As = smem;                   // [128][APITCH]
    __half* Ws = smem + 128 * APITCH;    // [128][APITCH]
    __shared__ float sbias[128];

    int tid = threadIdx.x;
    int lane = tid & 31;
    int wid = tid >> 5;
    int wrow = wid & 3;      // 4 row blocks of 32
    int wcol = wid >> 2;     // 2 col blocks of 64
    int n0 = blockIdx.x * 128;

    if (tid < 128) sbias[tid] = bias[tid];

    float acc[2][8][4];
#pragma unroll
    for (int mt = 0; mt < 2; mt++)
#pragma unroll
        for (int nt = 0; nt < 8; nt++)
#pragma unroll
            for (int q = 0; q < 4; q++) acc[mt][nt][q] = 0.f;

    uint32_t as_u = smem_u32(As);
    uint32_t ws_u = smem_u32(Ws);

#pragma unroll
    for (int s = 0; s < 2; s++) {
        const __half* Asrc = s ? Hf : Ah;
        const __half* Wsrc = Wc + s * 128 * 128;
        // cooperative load: 2048 16B chunks (A) + 2048 (W), 8 each per thread
#pragma unroll
        for (int rep = 0; rep < 8; rep++) {
            int c = tid + rep * 256;
            int r = c >> 4, c8 = c & 15;
            int n = n0 + r; if (n >= Nn) n = Nn - 1;
            *reinterpret_cast<uint4*>(As + r * APITCH + c8 * 8) =
                *reinterpret_cast<const uint4*>(Asrc + (size_t)n * 128 + c8 * 8);
            *reinterpret_cast<uint4*>(Ws + r * APITCH + c8 * 8) =
                *reinterpret_cast<const uint4*>(Wsrc + (size_t)r * 128 + c8 * 8);
        }
        __syncthreads();

#pragma unroll
        for (int kc = 0; kc < 8; kc++) {
            int k0 = kc * 16;
            uint32_t a[2][4];
#pragma unroll
            for (int mt = 0; mt < 2; mt++) {
                int r = wrow * 32 + mt * 16 + (lane & 15);
                uint32_t addr = as_u + (uint32_t)(r * APITCH + k0 + (lane >> 4) * 8) * 2;
                ldsm_x4(a[mt][0], a[mt][1], a[mt][2], a[mt][3], addr);
            }
#pragma unroll
            for (int nt2 = 0; nt2 < 4; nt2++) {
                int kr = k0 + (lane & 15);
                int nc = wcol * 64 + nt2 * 16 + (lane >> 4) * 8;
                uint32_t addr = ws_u + (uint32_t)(kr * APITCH + nc) * 2;
                uint32_t b0, b1, b2, b3;
                ldsm_x4t(b0, b1, b2, b3, addr);
#pragma unroll
                for (int mt = 0; mt < 2; mt++) {
                    mma16816(acc[mt][nt2 * 2],     a[mt], b0, b1);
                    mma16816(acc[mt][nt2 * 2 + 1], a[mt], b2, b3);
                }
            }
        }
        __syncthreads();
    }

    // epilogue: bias + relu -> fp16 (in-place safe: CTA read-set == write-set)
#pragma unroll
    for (int mt = 0; mt < 2; mt++) {
        int r0 = n0 + wrow * 32 + mt * 16 + (lane >> 2);
#pragma unroll
        for (int nt = 0; nt < 8; nt++) {
            int col = wcol * 64 + nt * 8 + (lane & 3) * 2;
            float b0 = sbias[col], b1 = sbias[col + 1];
            float v0 = fmaxf(acc[mt][nt][0] + b0, 0.f);
            float v1 = fmaxf(acc[mt][nt][1] + b1, 0.f);
            float v2 = fmaxf(acc[mt][nt][2] + b0, 0.f);
            float v3 = fmaxf(acc[mt][nt][3] + b1, 0.f);
            if (r0 < Nn)
                *reinterpret_cast<__half2*>(Hout + (size_t)r0 * 128 + col) =
                    __floats2half2_rn(v0, v1);
            if (r0 + 8 < Nn)
                *reinterpret_cast<__half2*>(Hout + (size_t)(r0 + 8) * 128 + col) =
                    __floats2half2_rn(v2, v3);
        }
    }
}

// ---------------- segmented mean pool (batch sorted, fp16 input) -----------------
__global__ void segpool_kernel(const __half* __restrict__ h,
                               const int* __restrict__ batch) {
    __shared__ int sbeg, send;
    int g = blockIdx.x;
    int j = threadIdx.x;
    if (j == 0) {
        int lo = 0, hi = Nn;
        while (lo < hi) { int mid = (lo + hi) >> 1; if (batch[mid] < g) lo = mid + 1; else hi = mid; }
        sbeg = lo;
        lo = 0; hi = Nn;
        while (lo < hi) { int mid = (lo + hi) >> 1; if (batch[mid] < g + 1) lo = mid + 1; else hi = mid; }
        send = lo;
    }
    __syncthreads();
    int beg = sbeg, end = send;
    float acc = 0.f;
    int r = beg;
    for (; r + 3 < end; r += 4) {
        acc += __half2float(h[(size_t)r * 128 + j]);
        acc += __half2float(h[(size_t)(r + 1) * 128 + j]);
        acc += __half2float(h[(size_t)(r + 2) * 128 + j]);
        acc += __half2float(h[(size_t)(r + 3) * 128 + j]);
    }
    for (; r < end; r++) acc += __half2float(h[(size_t)r * 128 + j]);
    float c = fmaxf((float)(end - beg), 1.0f);
    g_pool[g * 128 + j] = acc / c;
}

// ---------------- final MLP head: one block per graph ------------------------------
__global__ void mlp_kernel(const float* __restrict__ Wf1,
                           const float* __restrict__ bf1,
                           const float* __restrict__ Wf2,
                           const float* __restrict__ bf2,
                           float* __restrict__ out) {
    __shared__ float gs[128];
    __shared__ float red[128];
    int gi = blockIdx.x;
    int j = threadIdx.x;
    gs[j] = g_pool[gi * 128 + j];
    __syncthreads();
    float acc = bf1[j];
#pragma unroll 8
    for (int k = 0; k < 128; k++) acc += gs[k] * Wf1[k * 128 + j];
    float hid = fmaxf(acc, 0.0f);
    red[j] = hid * Wf2[j];
    __syncthreads();
    for (int s = 64; s > 0; s >>= 1) {
        if (j < s) red[j] += red[j + s];
        __syncthreads();
    }
    if (j == 0) out[gi] = 1.0f / (1.0f + expf(-(red[0] + bf2[0])));
}

// ---------------- launch --------------------------------------------------------------
extern "C" void kernel_launch(void* const* d_in, const int* in_sizes, int n_in,
                              void* d_out, int out_size) {
    const float* x = (const float*)d_in[0];
    const int* el = (const int*)d_in[1];
    const int* batch = (const int*)d_in[2];
    WPtrs wp;
    const float* bb[5];
    for (int i = 0; i < 5; i++) {
        wp.p[2 * i]     = (const float*)d_in[3 + 3 * i];   // Wl
        wp.p[2 * i + 1] = (const float*)d_in[4 + 3 * i];   // Wr
        bb[i] = (const float*)d_in[5 + 3 * i];
    }
    const float* Wf1 = (const float*)d_in[18];
    const float* bf1 = (const float*)d_in[19];
    const float* Wf2 = (const float*)d_in[20];
    const float* bf2 = (const float*)d_in[21];
    float* out = (float*)d_out;

    __half *hh, *aggh, *wcat;
    cudaGetSymbolAddress((void**)&hh, g_hh);
    cudaGetSymbolAddress((void**)&aggh, g_aggh);
    cudaGetSymbolAddress((void**)&wcat, g_wcat);

    static int smem_set = 0;
    const int dyn_smem = 2 * 128 * APITCH * 2;  // 69632 B
    if (!smem_set) {
        cudaFuncSetAttribute(gemm_mma, cudaFuncAttributeMaxDynamicSharedMemorySize, dyn_smem);
        smem_set = 1;
    }

    // prep + CSR build (gather is launch #6 -> ncu -s 5 profiles it)
    prep_kernel<<<(Nn * Hh / 2 + 255) / 256, 256>>>(x, wp);
    hist_kernel<<<(Ee + 255) / 256, 256>>>((const int2*)el);
    scan1_kernel<<<NSCAN_BLK, 1024>>>();
    scan3_kernel<<<(Nn + 255) / 256, 256>>>();
    fill_kernel<<<(Ee + 255) / 256, 256>>>((const int2*)el);

    // 5 layers: gather -> tensor-core GEMM (in-place hh update)
    for (int l = 0; l < 5; l++) {
        gather_kernel<<<(Nn * 32 + 255) / 256, 256>>>(hh);
        gemm_mma<<<NG_GEMM, 256, dyn_smem>>>(aggh, hh, wcat + (size_t)l * 256 * 128,
                                             bb[l], hh);
    }

    // segmented mean pool + parallel MLP head
    segpool_kernel<<<Gg, 128>>>(hh, batch);
    mlp_kernel<<<Gg, 128>>>(Wf1, bf1, Wf2, bf2, out);
}